// round 2
// baseline (speedup 1.0000x reference)
#include <cuda_runtime.h>
#include <math.h>

// ---------------------------------------------------------------------------
// SSIM (mean) for 64 x 1 x 512 x 512 fp32 image pairs, 11x11 Gaussian window.
//
//   - only conv(x), conv(y), conv(x^2+y^2), conv(x*y) are needed
//   - window is separable: g recovered from row 5 of the 2-D window
//   - fields processed as packed f32x2 pairs: (x,y) and (x^2+y^2, x*y)
//     using Blackwell fma.rn.f32x2 / add.rn.f32x2 (FFMA2)
//   - single kernel: last CTA (atomic ticket) reduces all partials
// ---------------------------------------------------------------------------

#define IMGW 512
#define IMGH 512
#define NIMG 64
#define TW 64
#define TH 32
#define RAD 5
#define IH (TH + 2*RAD)           // 42
#define IWD (TW + 2*RAD)          // 74
#define ISTR 75                   // float2 stride, staging (conflict-free)
#define HSTR 65                   // float2 stride, h-pass (conflict-free)
#define NTHREADS 256
#define TILES_X (IMGW / TW)       // 8
#define TILES_Y (IMGH / TH)       // 16
#define NBLOCKS (NIMG * TILES_X * TILES_Y)   // 8192

typedef unsigned long long u64;

__device__ float g_partials[NBLOCKS];
__device__ unsigned int g_ticket;   // zero-init; reset by last block each call

__device__ __forceinline__ u64 pk(float lo, float hi) {
    u64 r; asm("mov.b64 %0, {%1, %2};" : "=l"(r) : "f"(lo), "f"(hi)); return r;
}
__device__ __forceinline__ void upk(u64 v, float& lo, float& hi) {
    asm("mov.b64 {%0, %1}, %2;" : "=f"(lo), "=f"(hi) : "l"(v));
}
__device__ __forceinline__ u64 f2fma(u64 a, u64 b, u64 c) {
    u64 d; asm("fma.rn.f32x2 %0, %1, %2, %3;" : "=l"(d) : "l"(a), "l"(b), "l"(c)); return d;
}
__device__ __forceinline__ u64 f2add(u64 a, u64 b) {
    u64 d; asm("add.rn.f32x2 %0, %1, %2;" : "=l"(d) : "l"(a), "l"(b)); return d;
}
__device__ __forceinline__ u64 f2mul(u64 a, u64 b) {
    u64 d; asm("mul.rn.f32x2 %0, %1, %2;" : "=l"(d) : "l"(a), "l"(b)); return d;
}

// 11-tap symmetric conv, packed pair lanes: 18-value window -> 8 outputs.
__device__ __forceinline__ void conv8p(const u64 v[18], u64 out[8],
                                       u64 w0, u64 w1, u64 w2,
                                       u64 w3, u64 w4, u64 w5) {
#pragma unroll
    for (int j = 0; j < 8; j++) {
        u64 acc = f2mul(w5, v[j + 5]);
        acc = f2fma(w0, f2add(v[j + 0], v[j + 10]), acc);
        acc = f2fma(w1, f2add(v[j + 1], v[j + 9]),  acc);
        acc = f2fma(w2, f2add(v[j + 2], v[j + 8]),  acc);
        acc = f2fma(w3, f2add(v[j + 3], v[j + 7]),  acc);
        acc = f2fma(w4, f2add(v[j + 4], v[j + 6]),  acc);
        out[j] = acc;
    }
}

__global__ __launch_bounds__(NTHREADS, 2)
void ssim_fused_kernel(const float* __restrict__ img1,
                       const float* __restrict__ img2,
                       const float* __restrict__ win,
                       float* __restrict__ out) {
    extern __shared__ u64 sm8[];
    u64* sxy = sm8;                          // (x, y)            IH*ISTR
    u64* sce = sxy + IH * ISTR;              // (x^2+y^2, x*y)    IH*ISTR
    u64* hab = sce + IH * ISTR;              // h-pass pair 1     IH*HSTR
    u64* hce = hab + IH * HSTR;              // h-pass pair 2     IH*HSTR
    float* gw  = (float*)(hce + IH * HSTR);  // 11 (+pad)
    float* red = gw + 12;                    // 8
    __shared__ int s_isLast;

    const int tid = threadIdx.x;

    if (tid < 11) {
        float g5 = sqrtf(win[5 * 11 + 5]);
        gw[tid] = win[5 * 11 + tid] / g5;
    }

    // ---- Stage inputs (zero-padded halo) + pointwise products -------------
    const int imgoff = blockIdx.z * (IMGW * IMGH);
    const float* p1 = img1 + imgoff;
    const float* p2 = img2 + imgoff;
    const int bx0 = blockIdx.x * TW - RAD;
    const int by0 = blockIdx.y * TH - RAD;

    for (int i = tid; i < IH * IWD; i += NTHREADS) {
        int r = i / IWD;
        int c = i - r * IWD;
        int gx = bx0 + c;
        int gy = by0 + r;
        float x = 0.f, y = 0.f;
        if ((unsigned)gx < (unsigned)IMGW && (unsigned)gy < (unsigned)IMGH) {
            int o = gy * IMGW + gx;
            x = __ldg(p1 + o);
            y = __ldg(p2 + o);
        }
        int si = r * ISTR + c;
        sxy[si] = pk(x, y);
        sce[si] = pk(fmaf(x, x, y * y), x * y);
    }
    __syncthreads();

    const float w0s = gw[0], w1s = gw[1], w2s = gw[2],
                w3s = gw[3], w4s = gw[4], w5s = gw[5];
    const u64 w0 = pk(w0s, w0s), w1 = pk(w1s, w1s), w2 = pk(w2s, w2s),
              w3 = pk(w3s, w3s), w4 = pk(w4s, w4s), w5 = pk(w5s, w5s);

    // ---- Horizontal pass: 8-wide strips, 18-value register windows -------
    for (int s = tid; s < IH * (TW / 8); s += NTHREADS) {
        int r = s % IH;
        int cb = (s / IH) * 8;
        const int ib = r * ISTR + cb;
        const int ob = r * HSTR + cb;
        u64 v[18], o[8];

#pragma unroll
        for (int j = 0; j < 18; j++) v[j] = sxy[ib + j];
        conv8p(v, o, w0, w1, w2, w3, w4, w5);
#pragma unroll
        for (int j = 0; j < 8; j++) hab[ob + j] = o[j];

#pragma unroll
        for (int j = 0; j < 18; j++) v[j] = sce[ib + j];
        conv8p(v, o, w0, w1, w2, w3, w4, w5);
#pragma unroll
        for (int j = 0; j < 8; j++) hce[ob + j] = o[j];
    }
    __syncthreads();

    // ---- Vertical pass: each thread owns one column, 8 output rows --------
    const int c  = tid & (TW - 1);
    const int rb = (tid >> 6) * 8;
    u64 vab[8], vce[8];
    {
        u64 v[18];
#pragma unroll
        for (int j = 0; j < 18; j++) v[j] = hab[(rb + j) * HSTR + c];
        conv8p(v, vab, w0, w1, w2, w3, w4, w5);
#pragma unroll
        for (int j = 0; j < 18; j++) v[j] = hce[(rb + j) * HSTR + c];
        conv8p(v, vce, w0, w1, w2, w3, w4, w5);
    }

    // ---- SSIM map + local accumulation ------------------------------------
    const float C1 = 0.0001f;
    const float C2 = 0.0009f;
    float sum = 0.f;
#pragma unroll
    for (int j = 0; j < 8; j++) {
        float mu1, mu2, cc, ce;
        upk(vab[j], mu1, mu2);
        upk(vce[j], cc, ce);
        float m11 = mu1 * mu1;
        float m22 = mu2 * mu2;
        float m12 = mu1 * mu2;
        float s12  = ce - m12;
        float ssum = cc - m11 - m22;
        float num = fmaf(2.f, m12, C1) * fmaf(2.f, s12, C2);
        float den = (m11 + m22 + C1) * (ssum + C2);
        sum += __fdividef(num, den);
    }

    // ---- Block reduction --------------------------------------------------
#pragma unroll
    for (int o = 16; o; o >>= 1)
        sum += __shfl_down_sync(0xffffffffu, sum, o);
    if ((tid & 31) == 0) red[tid >> 5] = sum;
    __syncthreads();

    const int bi = (blockIdx.z * gridDim.y + blockIdx.y) * gridDim.x + blockIdx.x;
    if (tid == 0) {
        float t = 0.f;
#pragma unroll
        for (int w = 0; w < NTHREADS / 32; w++) t += red[w];
        g_partials[bi] = t;
        __threadfence();
        unsigned int tk = atomicAdd(&g_ticket, 1u);
        s_isLast = (tk == NBLOCKS - 1);
    }
    __syncthreads();

    // ---- Last CTA: deterministic final reduction --------------------------
    if (s_isLast) {
        float s = 0.f;
        for (int i = tid; i < NBLOCKS; i += NTHREADS)
            s += __ldcg(&g_partials[i]);
        red[0] = 0.f;  // reuse: warp partial slots
        __syncthreads();
#pragma unroll
        for (int o = 16; o; o >>= 1)
            s += __shfl_down_sync(0xffffffffu, s, o);
        if ((tid & 31) == 0) red[tid >> 5] = s;
        __syncthreads();
        if (tid == 0) {
            float t = 0.f;
#pragma unroll
            for (int w = 0; w < NTHREADS / 32; w++) t += red[w];
            out[0] = t * (1.0f / (float)((long long)NIMG * IMGW * IMGH));
            g_ticket = 0;   // reset for next (graph-replayed) call
        }
    }
}

extern "C" void kernel_launch(void* const* d_in, const int* in_sizes, int n_in,
                              void* d_out, int out_size) {
    const float* img1 = (const float*)d_in[0];
    const float* img2 = (const float*)d_in[1];
    const float* win  = (const float*)d_in[2];

    const size_t SMEM = (size_t)(2 * IH * ISTR + 2 * IH * HSTR) * sizeof(u64)
                      + 20 * sizeof(float);
    cudaFuncSetAttribute(ssim_fused_kernel,
                         cudaFuncAttributeMaxDynamicSharedMemorySize, (int)SMEM);

    dim3 grid(TILES_X, TILES_Y, NIMG);
    ssim_fused_kernel<<<grid, NTHREADS, SMEM>>>(img1, img2, win, (float*)d_out);
}

// round 5
// speedup vs baseline: 1.3297x; 1.3297x over previous
#include <cuda_runtime.h>
#include <math.h>

// ---------------------------------------------------------------------------
// SSIM (mean), 64 x 1 x 512 x 512 fp32 pairs, 11x11 Gaussian (separable).
//
// R5 (= R3 theory, third submission; prior two benches were broker failures):
//   - stage ONLY the packed (x,y) pair; (x^2+y^2, x*y) recomputed in-window
//   - tile 64x16 (IH=26): 42.6 KB smem/CTA
//   - 4-wide / 4-tall strips: 14-value windows, reduced peak live set
//   - __launch_bounds__(256, 4)  -> 4 CTAs/SM, 32 warps
//   - packed f32x2 math throughout, single fused kernel w/ ticket reduction
// ---------------------------------------------------------------------------

#define IMGW 512
#define IMGH 512
#define NIMG 64
#define TW 64
#define TH 16
#define RAD 5
#define IH (TH + 2*RAD)           // 26
#define IWD (TW + 2*RAD)          // 74
#define ISTR 75                   // u64 stride, staging (odd -> conflict free)
#define HSTR 65                   // u64 stride, h-pass out (odd -> conflict free)
#define NTHREADS 256
#define TILES_X (IMGW / TW)       // 8
#define TILES_Y (IMGH / TH)       // 32
#define NBLOCKS (NIMG * TILES_X * TILES_Y)   // 16384

typedef unsigned long long u64;

__device__ float g_partials[NBLOCKS];
__device__ unsigned int g_ticket;

__device__ __forceinline__ u64 pk(float lo, float hi) {
    u64 r; asm("mov.b64 %0, {%1, %2};" : "=l"(r) : "f"(lo), "f"(hi)); return r;
}
__device__ __forceinline__ void upk(u64 v, float& lo, float& hi) {
    asm("mov.b64 {%0, %1}, %2;" : "=f"(lo), "=f"(hi) : "l"(v));
}
__device__ __forceinline__ u64 f2fma(u64 a, u64 b, u64 c) {
    u64 d; asm("fma.rn.f32x2 %0, %1, %2, %3;" : "=l"(d) : "l"(a), "l"(b), "l"(c)); return d;
}
__device__ __forceinline__ u64 f2add(u64 a, u64 b) {
    u64 d; asm("add.rn.f32x2 %0, %1, %2;" : "=l"(d) : "l"(a), "l"(b)); return d;
}
__device__ __forceinline__ u64 f2mul(u64 a, u64 b) {
    u64 d; asm("mul.rn.f32x2 %0, %1, %2;" : "=l"(d) : "l"(a), "l"(b)); return d;
}

// 11-tap symmetric conv on a 14-value packed window -> 4 outputs.
__device__ __forceinline__ void conv4p(const u64 v[14], u64 out[4],
                                       u64 w0, u64 w1, u64 w2,
                                       u64 w3, u64 w4, u64 w5) {
#pragma unroll
    for (int j = 0; j < 4; j++) {
        u64 acc = f2mul(w5, v[j + 5]);
        acc = f2fma(w0, f2add(v[j + 0], v[j + 10]), acc);
        acc = f2fma(w1, f2add(v[j + 1], v[j + 9]),  acc);
        acc = f2fma(w2, f2add(v[j + 2], v[j + 8]),  acc);
        acc = f2fma(w3, f2add(v[j + 3], v[j + 7]),  acc);
        acc = f2fma(w4, f2add(v[j + 4], v[j + 6]),  acc);
        out[j] = acc;
    }
}

__global__ __launch_bounds__(NTHREADS, 4)
void ssim_fused_kernel(const float* __restrict__ img1,
                       const float* __restrict__ img2,
                       const float* __restrict__ win,
                       float* __restrict__ out) {
    extern __shared__ u64 sm8[];
    u64* sxy = sm8;                          // (x, y)            IH*ISTR
    u64* hab = sxy + IH * ISTR;              // h-pass (mu-pair)   IH*HSTR
    u64* hce = hab + IH * HSTR;              // h-pass (prod-pair) IH*HSTR
    float* gw  = (float*)(hce + IH * HSTR);  // 11 (+pad)
    float* red = gw + 12;                    // 8
    __shared__ int s_isLast;

    const int tid = threadIdx.x;

    if (tid < 11) {
        float g5 = sqrtf(win[5 * 11 + 5]);
        gw[tid] = win[5 * 11 + tid] / g5;
    }

    // ---- Stage packed (x,y) with zero-padded halo -------------------------
    const int imgoff = blockIdx.z * (IMGW * IMGH);
    const float* p1 = img1 + imgoff;
    const float* p2 = img2 + imgoff;
    const int bx0 = blockIdx.x * TW - RAD;
    const int by0 = blockIdx.y * TH - RAD;

    for (int i = tid; i < IH * IWD; i += NTHREADS) {
        int r = i / IWD;
        int c = i - r * IWD;
        int gx = bx0 + c;
        int gy = by0 + r;
        float x = 0.f, y = 0.f;
        if ((unsigned)gx < (unsigned)IMGW && (unsigned)gy < (unsigned)IMGH) {
            int o = gy * IMGW + gx;
            x = __ldg(p1 + o);
            y = __ldg(p2 + o);
        }
        sxy[r * ISTR + c] = pk(x, y);
    }
    __syncthreads();

    const float w0s = gw[0], w1s = gw[1], w2s = gw[2],
                w3s = gw[3], w4s = gw[4], w5s = gw[5];
    const u64 w0 = pk(w0s, w0s), w1 = pk(w1s, w1s), w2 = pk(w2s, w2s),
              w3 = pk(w3s, w3s), w4 = pk(w4s, w4s), w5 = pk(w5s, w5s);

    // ---- Horizontal pass: 4-wide strips, one 14-value load feeds both ----
    // 26 rows * 16 strips = 416 strips
    for (int s = tid; s < IH * (TW / 4); s += NTHREADS) {
        int r = s % IH;
        int cb = (s / IH) * 4;
        const int ib = r * ISTR + cb;
        const int ob = r * HSTR + cb;
        {
            u64 v[14], o[4];
#pragma unroll
            for (int j = 0; j < 14; j++) v[j] = sxy[ib + j];
            conv4p(v, o, w0, w1, w2, w3, w4, w5);
#pragma unroll
            for (int j = 0; j < 4; j++) hab[ob + j] = o[j];

            // transform window in place: (x,y) -> (x^2+y^2, x*y)
#pragma unroll
            for (int j = 0; j < 14; j++) {
                float x, y; upk(v[j], x, y);
                v[j] = pk(fmaf(x, x, y * y), x * y);
            }
            conv4p(v, o, w0, w1, w2, w3, w4, w5);
#pragma unroll
            for (int j = 0; j < 4; j++) hce[ob + j] = o[j];
        }
    }
    __syncthreads();

    // ---- Vertical pass: 4-tall column strips (256 strips exactly) ---------
    const int c  = tid & (TW - 1);          // 0..63
    const int rb = (tid >> 6) * 4;          // 0,4,8,12
    u64 vab[4], vce[4];
    {
        u64 v[14];
#pragma unroll
        for (int j = 0; j < 14; j++) v[j] = hab[(rb + j) * HSTR + c];
        conv4p(v, vab, w0, w1, w2, w3, w4, w5);
#pragma unroll
        for (int j = 0; j < 14; j++) v[j] = hce[(rb + j) * HSTR + c];
        conv4p(v, vce, w0, w1, w2, w3, w4, w5);
    }

    // ---- SSIM map + local accumulation ------------------------------------
    const float C1 = 0.0001f;
    const float C2 = 0.0009f;
    float sum = 0.f;
#pragma unroll
    for (int j = 0; j < 4; j++) {
        float mu1, mu2, cc, ce;
        upk(vab[j], mu1, mu2);
        upk(vce[j], cc, ce);
        float m11 = mu1 * mu1;
        float m22 = mu2 * mu2;
        float m12 = mu1 * mu2;
        float s12  = ce - m12;
        float ssum = cc - m11 - m22;
        float num = fmaf(2.f, m12, C1) * fmaf(2.f, s12, C2);
        float den = (m11 + m22 + C1) * (ssum + C2);
        sum += __fdividef(num, den);
    }

    // ---- Block reduction --------------------------------------------------
#pragma unroll
    for (int o = 16; o; o >>= 1)
        sum += __shfl_down_sync(0xffffffffu, sum, o);
    if ((tid & 31) == 0) red[tid >> 5] = sum;
    __syncthreads();

    const int bi = (blockIdx.z * gridDim.y + blockIdx.y) * gridDim.x + blockIdx.x;
    if (tid == 0) {
        float t = 0.f;
#pragma unroll
        for (int w = 0; w < NTHREADS / 32; w++) t += red[w];
        g_partials[bi] = t;
        __threadfence();
        unsigned int tk = atomicAdd(&g_ticket, 1u);
        s_isLast = (tk == NBLOCKS - 1);
    }
    __syncthreads();

    // ---- Last CTA: deterministic final reduction --------------------------
    if (s_isLast) {
        float s = 0.f;
        for (int i = tid; i < NBLOCKS; i += NTHREADS)
            s += g_partials[i];
        __syncthreads();
#pragma unroll
        for (int o = 16; o; o >>= 1)
            s += __shfl_down_sync(0xffffffffu, s, o);
        if ((tid & 31) == 0) red[tid >> 5] = s;
        __syncthreads();
        if (tid == 0) {
            float t = 0.f;
#pragma unroll
            for (int w = 0; w < NTHREADS / 32; w++) t += red[w];
            out[0] = t * (1.0f / (float)((long long)NIMG * IMGW * IMGH));
            g_ticket = 0;
        }
    }
}

extern "C" void kernel_launch(void* const* d_in, const int* in_sizes, int n_in,
                              void* d_out, int out_size) {
    const float* img1 = (const float*)d_in[0];
    const float* img2 = (const float*)d_in[1];
    const float* win  = (const float*)d_in[2];

    const size_t SMEM = (size_t)(IH * ISTR + 2 * IH * HSTR) * sizeof(u64)
                      + 20 * sizeof(float);
    cudaFuncSetAttribute(ssim_fused_kernel,
                         cudaFuncAttributeMaxDynamicSharedMemorySize, (int)SMEM);

    dim3 grid(TILES_X, TILES_Y, NIMG);
    ssim_fused_kernel<<<grid, NTHREADS, SMEM>>>(img1, img2, win, (float*)d_out);
}

// round 7
// speedup vs baseline: 1.6935x; 1.2736x over previous
#include <cuda_runtime.h>
#include <math.h>

// ---------------------------------------------------------------------------
// SSIM (mean), 64 x 1 x 512 x 512 fp32 pairs, 11x11 Gaussian (separable).
//
// R7 (= R6 resubmit; prior bench was a broker/container failure, no data):
// banded persistent tiles with ring buffers.
//   - CTA owns a 64-wide x 128-tall chunk, processed as 8 bands of 16 rows
//   - 32-row ring buffers (&31 indexing) for staged input and h-filtered data
//   - h-pass touches each image row exactly once (no vertical halo rework)
//   - stage of band b+1 overlapped with v-pass of band b (2 syncs/band)
//   - packed f32x2 math; single fused kernel w/ ticket reduction
// ---------------------------------------------------------------------------

#define IMGW 512
#define IMGH 512
#define NIMG 64
#define TW 64
#define TH 16
#define RAD 5
#define IWD (TW + 2*RAD)          // 74
#define ISTR 75                   // u64 stride, staging ring
#define HSTR 65                   // u64 stride, h-pass rings
#define RING 32
#define NTHREADS 256
#define TILES_X (IMGW / TW)       // 8
#define YCH 4                     // y-chunks per image column
#define CHROWS (IMGH / YCH)       // 128 rows per CTA
#define NBANDS (CHROWS / TH)      // 8
#define NBLOCKS (NIMG * TILES_X * YCH)   // 2048

typedef unsigned long long u64;

__device__ float g_partials[NBLOCKS];
__device__ unsigned int g_ticket;

__device__ __forceinline__ u64 pk(float lo, float hi) {
    u64 r; asm("mov.b64 %0, {%1, %2};" : "=l"(r) : "f"(lo), "f"(hi)); return r;
}
__device__ __forceinline__ void upk(u64 v, float& lo, float& hi) {
    asm("mov.b64 {%0, %1}, %2;" : "=f"(lo), "=f"(hi) : "l"(v));
}
__device__ __forceinline__ u64 f2fma(u64 a, u64 b, u64 c) {
    u64 d; asm("fma.rn.f32x2 %0, %1, %2, %3;" : "=l"(d) : "l"(a), "l"(b), "l"(c)); return d;
}
__device__ __forceinline__ u64 f2add(u64 a, u64 b) {
    u64 d; asm("add.rn.f32x2 %0, %1, %2;" : "=l"(d) : "l"(a), "l"(b)); return d;
}
__device__ __forceinline__ u64 f2mul(u64 a, u64 b) {
    u64 d; asm("mul.rn.f32x2 %0, %1, %2;" : "=l"(d) : "l"(a), "l"(b)); return d;
}

// 11-tap symmetric conv on a 14-value packed window -> 4 outputs.
__device__ __forceinline__ void conv4p(const u64 v[14], u64 out[4],
                                       u64 w0, u64 w1, u64 w2,
                                       u64 w3, u64 w4, u64 w5) {
#pragma unroll
    for (int j = 0; j < 4; j++) {
        u64 acc = f2mul(w5, v[j + 5]);
        acc = f2fma(w0, f2add(v[j + 0], v[j + 10]), acc);
        acc = f2fma(w1, f2add(v[j + 1], v[j + 9]),  acc);
        acc = f2fma(w2, f2add(v[j + 2], v[j + 8]),  acc);
        acc = f2fma(w3, f2add(v[j + 3], v[j + 7]),  acc);
        acc = f2fma(w4, f2add(v[j + 4], v[j + 6]),  acc);
        out[j] = acc;
    }
}

// Stage nrows global rows [g0, g0+nrows) into the sxy ring (zero-padded OOB).
__device__ __forceinline__ void stage_rows(u64* __restrict__ sxy,
                                           const float* __restrict__ p1,
                                           const float* __restrict__ p2,
                                           int bx0, int g0, int nrows, int tid) {
    const int total = nrows * IWD;
    for (int i = tid; i < total; i += NTHREADS) {
        int rr = i / IWD;
        int c  = i - rr * IWD;
        int gy = g0 + rr;
        int gx = bx0 + c;
        float x = 0.f, y = 0.f;
        if ((unsigned)gx < (unsigned)IMGW && (unsigned)gy < (unsigned)IMGH) {
            int o = gy * IMGW + gx;
            x = __ldg(p1 + o);
            y = __ldg(p2 + o);
        }
        sxy[(gy & (RING - 1)) * ISTR + c] = pk(x, y);
    }
}

// H-filter one 4-wide strip of global row `grow` at column base cb.
__device__ __forceinline__ void hstrip(const u64* __restrict__ sxy,
                                       u64* __restrict__ hab,
                                       u64* __restrict__ hce,
                                       int grow, int cb,
                                       u64 w0, u64 w1, u64 w2,
                                       u64 w3, u64 w4, u64 w5) {
    const int slot = grow & (RING - 1);
    const int ib = slot * ISTR + cb;
    const int ob = slot * HSTR + cb;
    u64 v[14], o[4];
#pragma unroll
    for (int j = 0; j < 14; j++) v[j] = sxy[ib + j];
    conv4p(v, o, w0, w1, w2, w3, w4, w5);
#pragma unroll
    for (int j = 0; j < 4; j++) hab[ob + j] = o[j];
#pragma unroll
    for (int j = 0; j < 14; j++) {
        float x, y; upk(v[j], x, y);
        v[j] = pk(fmaf(x, x, y * y), x * y);
    }
    conv4p(v, o, w0, w1, w2, w3, w4, w5);
#pragma unroll
    for (int j = 0; j < 4; j++) hce[ob + j] = o[j];
}

__global__ __launch_bounds__(NTHREADS, 4)
void ssim_fused_kernel(const float* __restrict__ img1,
                       const float* __restrict__ img2,
                       const float* __restrict__ win,
                       float* __restrict__ out) {
    extern __shared__ u64 sm8[];
    u64* sxy = sm8;                          // RING*ISTR  (x, y)
    u64* hab = sxy + RING * ISTR;            // RING*HSTR  h-filtered mu pair
    u64* hce = hab + RING * HSTR;            // RING*HSTR  h-filtered prod pair
    float* gw  = (float*)(hce + RING * HSTR);// 11 (+pad)
    float* red = gw + 12;                    // 8
    __shared__ int s_isLast;

    const int tid = threadIdx.x;

    if (tid < 11) {
        float g5 = sqrtf(win[5 * 11 + 5]);
        gw[tid] = win[5 * 11 + tid] / g5;
    }

    const int imgoff = blockIdx.z * (IMGW * IMGH);
    const float* p1 = img1 + imgoff;
    const float* p2 = img2 + imgoff;
    const int bx0 = blockIdx.x * TW - RAD;
    const int Y0  = blockIdx.y * CHROWS;

    // ---- Prologue: stage rows [Y0-5, Y0+21), h-filter them (26 rows) ------
    stage_rows(sxy, p1, p2, bx0, Y0 - RAD, TH + 2 * RAD, tid);
    __syncthreads();

    const float w0s = gw[0], w1s = gw[1], w2s = gw[2],
                w3s = gw[3], w4s = gw[4], w5s = gw[5];
    const u64 w0 = pk(w0s, w0s), w1 = pk(w1s, w1s), w2 = pk(w2s, w2s),
              w3 = pk(w3s, w3s), w4 = pk(w4s, w4s), w5 = pk(w5s, w5s);

    // prologue h-pass: 26 rows * 16 strips = 416 strips
    for (int s = tid; s < (TH + 2 * RAD) * (TW / 4); s += NTHREADS) {
        int r  = s >> 4;              // 0..25
        int cb = (s & 15) << 2;       // 0,4,...,60
        hstrip(sxy, hab, hce, Y0 - RAD + r, cb, w0, w1, w2, w3, w4, w5);
    }
    __syncthreads();

    // ---- Band loop --------------------------------------------------------
    const float C1 = 0.0001f;
    const float C2 = 0.0009f;
    const int c  = tid & (TW - 1);          // 0..63
    const int r4 = (tid >> 6) * 4;          // 0,4,8,12
    float sum = 0.f;

    for (int b = 0; b < NBANDS; b++) {
        const int B = Y0 + b * TH;

        // Phase A: v-pass of band b (reads hab/hce only), then overlapped
        // stage of band b+1 (writes sxy only -> no hazard with v-pass reads)
        {
            const int rb = B + r4;          // first output row of this strip
            u64 v[14], vab[4], vce[4];
#pragma unroll
            for (int j = 0; j < 14; j++)
                v[j] = hab[((rb - RAD + j) & (RING - 1)) * HSTR + c];
            conv4p(v, vab, w0, w1, w2, w3, w4, w5);
#pragma unroll
            for (int j = 0; j < 14; j++)
                v[j] = hce[((rb - RAD + j) & (RING - 1)) * HSTR + c];
            conv4p(v, vce, w0, w1, w2, w3, w4, w5);

#pragma unroll
            for (int j = 0; j < 4; j++) {
                float mu1, mu2, cc, ce;
                upk(vab[j], mu1, mu2);
                upk(vce[j], cc, ce);
                float m11 = mu1 * mu1;
                float m22 = mu2 * mu2;
                float m12 = mu1 * mu2;
                float s12  = ce - m12;
                float ssum = cc - m11 - m22;
                float num = fmaf(2.f, m12, C1) * fmaf(2.f, s12, C2);
                float den = (m11 + m22 + C1) * (ssum + C2);
                sum += __fdividef(num, den);
            }
        }
        if (b + 1 < NBANDS)
            stage_rows(sxy, p1, p2, bx0, B + TH + RAD, TH, tid);
        __syncthreads();

        // Phase B: h-pass rows [B+21, B+37) for band b+1 (256 strips, 1/thread)
        if (b + 1 < NBANDS) {
            int r  = tid & 15;
            int cb = (tid >> 4) << 2;
            hstrip(sxy, hab, hce, B + TH + RAD + r, cb, w0, w1, w2, w3, w4, w5);
            __syncthreads();
        }
    }

    // ---- Block reduction --------------------------------------------------
#pragma unroll
    for (int o = 16; o; o >>= 1)
        sum += __shfl_down_sync(0xffffffffu, sum, o);
    if ((tid & 31) == 0) red[tid >> 5] = sum;
    __syncthreads();

    const int bi = (blockIdx.z * gridDim.y + blockIdx.y) * gridDim.x + blockIdx.x;
    if (tid == 0) {
        float t = 0.f;
#pragma unroll
        for (int w = 0; w < NTHREADS / 32; w++) t += red[w];
        g_partials[bi] = t;
        __threadfence();
        unsigned int tk = atomicAdd(&g_ticket, 1u);
        s_isLast = (tk == NBLOCKS - 1);
    }
    __syncthreads();

    // ---- Last CTA: deterministic final reduction --------------------------
    if (s_isLast) {
        float s = 0.f;
        for (int i = tid; i < NBLOCKS; i += NTHREADS)
            s += g_partials[i];
        __syncthreads();
#pragma unroll
        for (int o = 16; o; o >>= 1)
            s += __shfl_down_sync(0xffffffffu, s, o);
        if ((tid & 31) == 0) red[tid >> 5] = s;
        __syncthreads();
        if (tid == 0) {
            float t = 0.f;
#pragma unroll
            for (int w = 0; w < NTHREADS / 32; w++) t += red[w];
            out[0] = t * (1.0f / (float)((long long)NIMG * IMGW * IMGH));
            g_ticket = 0;
        }
    }
}

extern "C" void kernel_launch(void* const* d_in, const int* in_sizes, int n_in,
                              void* d_out, int out_size) {
    const float* img1 = (const float*)d_in[0];
    const float* img2 = (const float*)d_in[1];
    const float* win  = (const float*)d_in[2];

    const size_t SMEM = (size_t)(RING * ISTR + 2 * RING * HSTR) * sizeof(u64)
                      + 20 * sizeof(float);
    cudaFuncSetAttribute(ssim_fused_kernel,
                         cudaFuncAttributeMaxDynamicSharedMemorySize, (int)SMEM);

    dim3 grid(TILES_X, YCH, NIMG);
    ssim_fused_kernel<<<grid, NTHREADS, SMEM>>>(img1, img2, win, (float*)d_out);
}

// round 8
// speedup vs baseline: 1.8675x; 1.1027x over previous
#include <cuda_runtime.h>
#include <math.h>

// ---------------------------------------------------------------------------
// SSIM (mean), 64 x 1 x 512 x 512 fp32 pairs, 11x11 Gaussian (separable).
//
// R8: instruction-volume cut on top of R7's banded rings.
//   - h arrays TRANSPOSED to column-major [col*33 + (row&31)]:
//     v-pass address = base + AND+ADD (was IMAD+AND per element)
//   - rolling accumulators both passes (same FMA count, smaller live sets)
//   - v-pass 8-tall strips: 4.5 LDS/px (was 7)
//   - sxy ring shrunk to 16 rows (prologue staged 16+10); smem 43.4 KB
// ---------------------------------------------------------------------------

#define IMGW 512
#define IMGH 512
#define NIMG 64
#define TW 64
#define TH 16
#define RAD 5
#define IWD (TW + 2*RAD)          // 74
#define ISTR 75                   // u64 stride, staging ring (odd -> no conflicts)
#define SRING 16                  // staging ring rows
#define HRING 32                  // h-array ring rows
#define HST 33                    // u64 per column in transposed h arrays
#define NTHREADS 256
#define TILES_X (IMGW / TW)       // 8
#define YCH 4
#define CHROWS (IMGH / YCH)       // 128
#define NBANDS (CHROWS / TH)      // 8
#define NBLOCKS (NIMG * TILES_X * YCH)   // 2048

typedef unsigned long long u64;

__device__ float g_partials[NBLOCKS];
__device__ unsigned int g_ticket;

__device__ __forceinline__ u64 pk(float lo, float hi) {
    u64 r; asm("mov.b64 %0, {%1, %2};" : "=l"(r) : "f"(lo), "f"(hi)); return r;
}
__device__ __forceinline__ void upk(u64 v, float& lo, float& hi) {
    asm("mov.b64 {%0, %1}, %2;" : "=f"(lo), "=f"(hi) : "l"(v));
}
__device__ __forceinline__ u64 f2fma(u64 a, u64 b, u64 c) {
    u64 d; asm("fma.rn.f32x2 %0, %1, %2, %3;" : "=l"(d) : "l"(a), "l"(b), "l"(c)); return d;
}
__device__ __forceinline__ u64 f2mul(u64 a, u64 b) {
    u64 d; asm("mul.rn.f32x2 %0, %1, %2;" : "=l"(d) : "l"(a), "l"(b)); return d;
}

// Stage nrows global rows [g0, g0+nrows) into the sxy ring (zero-padded OOB).
__device__ __forceinline__ void stage_rows(u64* __restrict__ sxy,
                                           const float* __restrict__ p1,
                                           const float* __restrict__ p2,
                                           int bx0, int g0, int nrows, int tid) {
    const int total = nrows * IWD;
    for (int i = tid; i < total; i += NTHREADS) {
        int rr = i / IWD;
        int c  = i - rr * IWD;
        int gy = g0 + rr;
        int gx = bx0 + c;
        float x = 0.f, y = 0.f;
        if ((unsigned)gx < (unsigned)IMGW && (unsigned)gy < (unsigned)IMGH) {
            int o = gy * IMGW + gx;
            x = __ldg(p1 + o);
            y = __ldg(p2 + o);
        }
        sxy[(gy & (SRING - 1)) * ISTR + c] = pk(x, y);
    }
}

// Rolling 4-wide h strip: row grow, output cols cb..cb+3, writes transposed.
__device__ __forceinline__ void hstrip4(const u64* __restrict__ sxy,
                                        u64* __restrict__ hab,
                                        u64* __restrict__ hce,
                                        int grow, int cb,
                                        const u64* __restrict__ W) {
    const int slot = grow & (HRING - 1);
    const int ib = (grow & (SRING - 1)) * ISTR + cb;
    u64 aab[4], ace[4];
#pragma unroll
    for (int j = 0; j < 14; j++) {
        u64 cur = sxy[ib + j];
        float x, y; upk(cur, x, y);
        u64 tr = pk(fmaf(x, x, y * y), x * y);
        const int klo = (j - 10) > 0 ? (j - 10) : 0;
        const int khi = j < 3 ? j : 3;
#pragma unroll
        for (int k = klo; k <= khi; k++) {
            if (k == j) { aab[k] = f2mul(W[0], cur); ace[k] = f2mul(W[0], tr); }
            else        { aab[k] = f2fma(W[j - k], cur, aab[k]);
                          ace[k] = f2fma(W[j - k], tr,  ace[k]); }
        }
    }
#pragma unroll
    for (int k = 0; k < 4; k++) {
        hab[(cb + k) * HST + slot] = aab[k];
        hce[(cb + k) * HST + slot] = ace[k];
    }
}

__global__ __launch_bounds__(NTHREADS, 4)
void ssim_fused_kernel(const float* __restrict__ img1,
                       const float* __restrict__ img2,
                       const float* __restrict__ win,
                       float* __restrict__ out) {
    extern __shared__ u64 sm8[];
    u64* sxy = sm8;                          // SRING*ISTR = 1200
    u64* hab = sxy + SRING * ISTR;           // TW*HST = 2112 (column-major)
    u64* hce = hab + TW * HST;               // 2112
    float* gw  = (float*)(hce + TW * HST);   // 11 (+pad)
    float* red = gw + 12;                    // 8
    __shared__ int s_isLast;

    const int tid = threadIdx.x;

    if (tid < 11) {
        float g5 = sqrtf(win[5 * 11 + 5]);
        gw[tid] = win[5 * 11 + tid] / g5;
    }

    const int imgoff = blockIdx.z * (IMGW * IMGH);
    const float* p1 = img1 + imgoff;
    const float* p2 = img2 + imgoff;
    const int bx0 = blockIdx.x * TW - RAD;
    const int Y0  = blockIdx.y * CHROWS;

    // ---- Prologue part 1: stage rows [Y0-5, Y0+11) ------------------------
    stage_rows(sxy, p1, p2, bx0, Y0 - RAD, 16, tid);
    __syncthreads();

    const float w0s = gw[0], w1s = gw[1], w2s = gw[2],
                w3s = gw[3], w4s = gw[4], w5s = gw[5];
    const u64 W[11] = { pk(w0s, w0s), pk(w1s, w1s), pk(w2s, w2s),
                        pk(w3s, w3s), pk(w4s, w4s), pk(w5s, w5s),
                        pk(w4s, w4s), pk(w3s, w3s), pk(w2s, w2s),
                        pk(w1s, w1s), pk(w0s, w0s) };

    // h-filter those 16 rows: 16 rows * 16 strips = 256 tasks
    {
        int r  = tid & 15;
        int cb = (tid >> 4) << 2;
        hstrip4(sxy, hab, hce, Y0 - RAD + r, cb, W);
    }
    __syncthreads();

    // ---- Prologue part 2: stage rows [Y0+11, Y0+21), h-filter -------------
    stage_rows(sxy, p1, p2, bx0, Y0 + 11, 10, tid);
    __syncthreads();
    if (tid < 160) {
        int r  = tid >> 4;            // 0..9
        int cb = (tid & 15) << 2;
        hstrip4(sxy, hab, hce, Y0 + 11 + r, cb, W);
    }
    __syncthreads();

    // ---- Band loop --------------------------------------------------------
    const float C1 = 0.0001f;
    const float C2 = 0.0009f;
    float sum = 0.f;

    for (int b = 0; b < NBANDS; b++) {
        const int B = Y0 + b * TH;

        // Phase A: v-pass of band b (tid<128: 64 cols x 2 groups of 8 rows),
        // then overlapped stage of band b+1 (all threads; writes sxy only).
        if (tid < 128) {
            const int c  = tid & 63;
            const int rb = B + ((tid >> 6) << 3);   // B or B+8
            const int ba = c * HST;
            const int bc = ba + TW * HST;           // hce = hab + TW*HST
            u64 aab[8], ace[8];
#pragma unroll
            for (int j = 0; j < 18; j++) {
                const int slot = (rb - RAD + j) & (HRING - 1);
                u64 va = hab[ba + slot];
                u64 vc = hab[bc + slot];
                const int klo = (j - 10) > 0 ? (j - 10) : 0;
                const int khi = j < 7 ? j : 7;
#pragma unroll
                for (int k = klo; k <= khi; k++) {
                    if (k == j) { aab[k] = f2mul(W[0], va); ace[k] = f2mul(W[0], vc); }
                    else        { aab[k] = f2fma(W[j - k], va, aab[k]);
                                  ace[k] = f2fma(W[j - k], vc, ace[k]); }
                }
            }
#pragma unroll
            for (int k = 0; k < 8; k++) {
                float mu1, mu2, cc, ce;
                upk(aab[k], mu1, mu2);
                upk(ace[k], cc, ce);
                float m11 = mu1 * mu1;
                float m22 = mu2 * mu2;
                float m12 = mu1 * mu2;
                float s12  = ce - m12;
                float ssum = cc - m11 - m22;
                float num = fmaf(2.f, m12, C1) * fmaf(2.f, s12, C2);
                float den = (m11 + m22 + C1) * (ssum + C2);
                sum += __fdividef(num, den);
            }
        }
        if (b + 1 < NBANDS)
            stage_rows(sxy, p1, p2, bx0, B + TH + RAD, TH, tid);
        __syncthreads();

        // Phase B: h-pass rows [B+21, B+37) (16 rows x 16 strips = 256 tasks)
        if (b + 1 < NBANDS) {
            int r  = tid & 15;
            int cb = (tid >> 4) << 2;
            hstrip4(sxy, hab, hce, B + TH + RAD + r, cb, W);
            __syncthreads();
        }
    }

    // ---- Block reduction --------------------------------------------------
#pragma unroll
    for (int o = 16; o; o >>= 1)
        sum += __shfl_down_sync(0xffffffffu, sum, o);
    if ((tid & 31) == 0) red[tid >> 5] = sum;
    __syncthreads();

    const int bi = (blockIdx.z * gridDim.y + blockIdx.y) * gridDim.x + blockIdx.x;
    if (tid == 0) {
        float t = 0.f;
#pragma unroll
        for (int w = 0; w < NTHREADS / 32; w++) t += red[w];
        g_partials[bi] = t;
        __threadfence();
        unsigned int tk = atomicAdd(&g_ticket, 1u);
        s_isLast = (tk == NBLOCKS - 1);
    }
    __syncthreads();

    // ---- Last CTA: deterministic final reduction --------------------------
    if (s_isLast) {
        float s = 0.f;
        for (int i = tid; i < NBLOCKS; i += NTHREADS)
            s += g_partials[i];
        __syncthreads();
#pragma unroll
        for (int o = 16; o; o >>= 1)
            s += __shfl_down_sync(0xffffffffu, s, o);
        if ((tid & 31) == 0) red[tid >> 5] = s;
        __syncthreads();
        if (tid == 0) {
            float t = 0.f;
#pragma unroll
            for (int w = 0; w < NTHREADS / 32; w++) t += red[w];
            out[0] = t * (1.0f / (float)((long long)NIMG * IMGW * IMGH));
            g_ticket = 0;
        }
    }
}

extern "C" void kernel_launch(void* const* d_in, const int* in_sizes, int n_in,
                              void* d_out, int out_size) {
    const float* img1 = (const float*)d_in[0];
    const float* img2 = (const float*)d_in[1];
    const float* win  = (const float*)d_in[2];

    const size_t SMEM = (size_t)(SRING * ISTR + 2 * TW * HST) * sizeof(u64)
                      + 20 * sizeof(float);
    cudaFuncSetAttribute(ssim_fused_kernel,
                         cudaFuncAttributeMaxDynamicSharedMemorySize, (int)SMEM);

    dim3 grid(TILES_X, YCH, NIMG);
    ssim_fused_kernel<<<grid, NTHREADS, SMEM>>>(img1, img2, win, (float*)d_out);
}

// round 10
// speedup vs baseline: 2.5225x; 1.3507x over previous
#include <cuda_runtime.h>
#include <math.h>

// ---------------------------------------------------------------------------
// SSIM (mean), 64 x 1 x 512 x 512 fp32 pairs, 11x11 Gaussian (separable).
//
// R10 (= R9 resubmit; prior bench was a broker/container failure, no data):
// address-ALU elimination on top of R8's banded-ring design.
//   - v-pass ring slots templated on compile-time start slot S0 in
//     {27,3,11,19} -> all 36 LDS use immediate offsets (zero address ALU)
//   - division-free staging (r = tid>>4, c0 = tid&15, 5 unrolled steps)
//   - h arrays column-major [col*33 + slot]; rolling accumulators both passes
// ---------------------------------------------------------------------------

#define IMGW 512
#define IMGH 512
#define NIMG 64
#define TW 64
#define TH 16
#define RAD 5
#define IWD (TW + 2*RAD)          // 74
#define ISTR 75
#define SRING 16
#define HRING 32
#define HST 33
#define NTHREADS 256
#define TILES_X (IMGW / TW)       // 8
#define YCH 4
#define CHROWS (IMGH / YCH)       // 128
#define NBANDS (CHROWS / TH)      // 8
#define NBLOCKS (NIMG * TILES_X * YCH)   // 2048

typedef unsigned long long u64;

__device__ float g_partials[NBLOCKS];
__device__ unsigned int g_ticket;

__device__ __forceinline__ u64 pk(float lo, float hi) {
    u64 r; asm("mov.b64 %0, {%1, %2};" : "=l"(r) : "f"(lo), "f"(hi)); return r;
}
__device__ __forceinline__ void upk(u64 v, float& lo, float& hi) {
    asm("mov.b64 {%0, %1}, %2;" : "=f"(lo), "=f"(hi) : "l"(v));
}
__device__ __forceinline__ u64 f2fma(u64 a, u64 b, u64 c) {
    u64 d; asm("fma.rn.f32x2 %0, %1, %2, %3;" : "=l"(d) : "l"(a), "l"(b), "l"(c)); return d;
}
__device__ __forceinline__ u64 f2mul(u64 a, u64 b) {
    u64 d; asm("mul.rn.f32x2 %0, %1, %2;" : "=l"(d) : "l"(a), "l"(b)); return d;
}

// Division-free stage of `nrows` rows [g0, g0+nrows) into the sxy ring.
// Layout: r = tid>>4 (16 rows max), c0 = tid&15, 5 unrolled column steps
// (80 lanes-worth of columns >= IWD=74; tail guarded).
__device__ __forceinline__ void stageN(u64* __restrict__ sxy,
                                       const float* __restrict__ p1,
                                       const float* __restrict__ p2,
                                       int bx0, int g0, int nrows, int tid) {
    const int r  = tid >> 4;
    const int c0 = tid & 15;
    if (r >= nrows) return;
    const int gy = g0 + r;
    const bool rowok = (unsigned)gy < (unsigned)IMGH;
    const float* q1 = p1 + gy * IMGW;
    const float* q2 = p2 + gy * IMGW;
    const int base = (gy & (SRING - 1)) * ISTR;
#pragma unroll
    for (int k = 0; k < 5; k++) {
        const int c = c0 + (k << 4);
        if (c < IWD) {
            const int gx = bx0 + c;
            float x = 0.f, y = 0.f;
            if (rowok && (unsigned)gx < (unsigned)IMGW) {
                x = __ldg(q1 + gx);
                y = __ldg(q2 + gx);
            }
            sxy[base + c] = pk(x, y);
        }
    }
}

// Rolling 4-wide h strip: row grow, output cols cb..cb+3, transposed write.
__device__ __forceinline__ void hstrip4(const u64* __restrict__ sxy,
                                        u64* __restrict__ hab,
                                        u64* __restrict__ hce,
                                        int grow, int cb,
                                        const u64* __restrict__ W) {
    const int slot = grow & (HRING - 1);
    const int ib = (grow & (SRING - 1)) * ISTR + cb;
    const int ob = cb * HST + slot;
    u64 aab[4], ace[4];
#pragma unroll
    for (int j = 0; j < 14; j++) {
        u64 cur = sxy[ib + j];
        float x, y; upk(cur, x, y);
        u64 tr = pk(fmaf(x, x, y * y), x * y);
        const int klo = (j - 10) > 0 ? (j - 10) : 0;
        const int khi = j < 3 ? j : 3;
#pragma unroll
        for (int k = klo; k <= khi; k++) {
            if (k == j) { aab[k] = f2mul(W[0], cur); ace[k] = f2mul(W[0], tr); }
            else        { aab[k] = f2fma(W[j - k], cur, aab[k]);
                          ace[k] = f2fma(W[j - k], tr,  ace[k]); }
        }
    }
#pragma unroll
    for (int k = 0; k < 4; k++) {
        hab[ob + k * HST] = aab[k];
        hce[ob + k * HST] = ace[k];
    }
}

// V-pass + SSIM for one column, 8 output rows. S0 = compile-time start slot
// -> every LDS offset is an immediate.
template<int S0>
__device__ __forceinline__ float vssim8(const u64* __restrict__ ha,
                                        const u64* __restrict__ hc,
                                        const u64* __restrict__ W) {
    u64 aab[8], ace[8];
#pragma unroll
    for (int j = 0; j < 18; j++) {
        const int slot = (S0 + j) & (HRING - 1);   // compile-time constant
        u64 va = ha[slot];
        u64 vc = hc[slot];
        const int klo = (j - 10) > 0 ? (j - 10) : 0;
        const int khi = j < 7 ? j : 7;
#pragma unroll
        for (int k = klo; k <= khi; k++) {
            if (k == j) { aab[k] = f2mul(W[0], va); ace[k] = f2mul(W[0], vc); }
            else        { aab[k] = f2fma(W[j - k], va, aab[k]);
                          ace[k] = f2fma(W[j - k], vc, ace[k]); }
        }
    }
    const float C1 = 0.0001f;
    const float C2 = 0.0009f;
    float sum = 0.f;
#pragma unroll
    for (int k = 0; k < 8; k++) {
        float mu1, mu2, cc, ce;
        upk(aab[k], mu1, mu2);
        upk(ace[k], cc, ce);
        float m11 = mu1 * mu1;
        float m22 = mu2 * mu2;
        float m12 = mu1 * mu2;
        float s12  = ce - m12;
        float ssum = cc - m11 - m22;
        float num = fmaf(2.f, m12, C1) * fmaf(2.f, s12, C2);
        float den = (m11 + m22 + C1) * (ssum + C2);
        sum += __fdividef(num, den);
    }
    return sum;
}

__global__ __launch_bounds__(NTHREADS, 4)
void ssim_fused_kernel(const float* __restrict__ img1,
                       const float* __restrict__ img2,
                       const float* __restrict__ win,
                       float* __restrict__ out) {
    extern __shared__ u64 sm8[];
    u64* sxy = sm8;                          // SRING*ISTR
    u64* hab = sxy + SRING * ISTR;           // TW*HST (column-major)
    u64* hce = hab + TW * HST;               // TW*HST
    float* gw  = (float*)(hce + TW * HST);   // 11 (+pad)
    float* red = gw + 12;                    // 8
    __shared__ int s_isLast;

    const int tid = threadIdx.x;

    if (tid < 11) {
        float g5 = sqrtf(win[5 * 11 + 5]);
        gw[tid] = win[5 * 11 + tid] / g5;
    }

    const int imgoff = blockIdx.z * (IMGW * IMGH);
    const float* p1 = img1 + imgoff;
    const float* p2 = img2 + imgoff;
    const int bx0 = blockIdx.x * TW - RAD;
    const int Y0  = blockIdx.y * CHROWS;

    // ---- Prologue part 1: rows [Y0-5, Y0+11) ------------------------------
    stageN(sxy, p1, p2, bx0, Y0 - RAD, 16, tid);
    __syncthreads();

    const float w0s = gw[0], w1s = gw[1], w2s = gw[2],
                w3s = gw[3], w4s = gw[4], w5s = gw[5];
    const u64 W[11] = { pk(w0s, w0s), pk(w1s, w1s), pk(w2s, w2s),
                        pk(w3s, w3s), pk(w4s, w4s), pk(w5s, w5s),
                        pk(w4s, w4s), pk(w3s, w3s), pk(w2s, w2s),
                        pk(w1s, w1s), pk(w0s, w0s) };

    // h-filter those 16 rows: 16 rows x 16 strips = 256 tasks, one per thread
    {
        int r  = tid & 15;
        int cb = (tid >> 4) << 2;
        hstrip4(sxy, hab, hce, Y0 - RAD + r, cb, W);
    }
    __syncthreads();

    // ---- Prologue part 2: rows [Y0+11, Y0+21) -----------------------------
    stageN(sxy, p1, p2, bx0, Y0 + 11, 10, tid);
    __syncthreads();
    if (tid < 160) {
        int r  = tid >> 4;            // 0..9
        int cb = (tid & 15) << 2;
        hstrip4(sxy, hab, hce, Y0 + 11 + r, cb, W);
    }
    __syncthreads();

    // ---- Band loop --------------------------------------------------------
    float sum = 0.f;

    for (int b = 0; b < NBANDS; b++) {
        const int B = Y0 + b * TH;

        // Phase A: v-pass (tid<128), then stage band b+1 (all threads).
        // Start slot s0 = (B + 8g - 5) & 31 with B%32 = 16*(b&1):
        //   b even: g0 -> 27, g1 -> 3 ; b odd: g0 -> 11, g1 -> 19
        if (tid < 128) {
            const int c = tid & 63;
            const int g = tid >> 6;
            const u64* ha = hab + c * HST;
            const u64* hc = hce + c * HST;
            if ((b & 1) == 0)
                sum += g ? vssim8<3>(ha, hc, W)  : vssim8<27>(ha, hc, W);
            else
                sum += g ? vssim8<19>(ha, hc, W) : vssim8<11>(ha, hc, W);
        }
        if (b + 1 < NBANDS)
            stageN(sxy, p1, p2, bx0, B + TH + RAD, TH, tid);
        __syncthreads();

        // Phase B: h-pass rows [B+21, B+37) (16 rows x 16 strips)
        if (b + 1 < NBANDS) {
            int r  = tid & 15;
            int cb = (tid >> 4) << 2;
            hstrip4(sxy, hab, hce, B + TH + RAD + r, cb, W);
            __syncthreads();
        }
    }

    // ---- Block reduction --------------------------------------------------
#pragma unroll
    for (int o = 16; o; o >>= 1)
        sum += __shfl_down_sync(0xffffffffu, sum, o);
    if ((tid & 31) == 0) red[tid >> 5] = sum;
    __syncthreads();

    const int bi = (blockIdx.z * gridDim.y + blockIdx.y) * gridDim.x + blockIdx.x;
    if (tid == 0) {
        float t = 0.f;
#pragma unroll
        for (int w = 0; w < NTHREADS / 32; w++) t += red[w];
        g_partials[bi] = t;
        __threadfence();
        unsigned int tk = atomicAdd(&g_ticket, 1u);
        s_isLast = (tk == NBLOCKS - 1);
    }
    __syncthreads();

    // ---- Last CTA: deterministic final reduction --------------------------
    if (s_isLast) {
        float s = 0.f;
        for (int i = tid; i < NBLOCKS; i += NTHREADS)
            s += g_partials[i];
        __syncthreads();
#pragma unroll
        for (int o = 16; o; o >>= 1)
            s += __shfl_down_sync(0xffffffffu, s, o);
        if ((tid & 31) == 0) red[tid >> 5] = s;
        __syncthreads();
        if (tid == 0) {
            float t = 0.f;
#pragma unroll
            for (int w = 0; w < NTHREADS / 32; w++) t += red[w];
            out[0] = t * (1.0f / (float)((long long)NIMG * IMGW * IMGH));
            g_ticket = 0;
        }
    }
}

extern "C" void kernel_launch(void* const* d_in, const int* in_sizes, int n_in,
                              void* d_out, int out_size) {
    const float* img1 = (const float*)d_in[0];
    const float* img2 = (const float*)d_in[1];
    const float* win  = (const float*)d_in[2];

    const size_t SMEM = (size_t)(SRING * ISTR + 2 * TW * HST) * sizeof(u64)
                      + 20 * sizeof(float);
    cudaFuncSetAttribute(ssim_fused_kernel,
                         cudaFuncAttributeMaxDynamicSharedMemorySize, (int)SMEM);

    dim3 grid(TILES_X, YCH, NIMG);
    ssim_fused_kernel<<<grid, NTHREADS, SMEM>>>(img1, img2, win, (float*)d_out);
}